// round 12
// baseline (speedup 1.0000x reference)
#include <cuda_runtime.h>
#include <cuda_bf16.h>
#include <cstddef>

typedef unsigned long long ull;

// ---------------------------------------------------------------------------
// Static device scratch (no allocation anywhere)
// ---------------------------------------------------------------------------
#define B_ 32
#define T_ 128
#define H_ 1024
#define E_ 512
#define V_ 32000
#define MROWS 4096  // T_*B_

__device__ float d_expanded[B_ * H_];              // [b][H]
__device__ float d_hbuf[2][2][B_ * H_];            // [phase][dir][b][H]
__device__ float d_seq[MROWS * H_];                // [t*B+b][H]
__device__ float d_pre0[MROWS * 2 * H_];           // [t*B+b][2H]  (cols: dir*H+j)
__device__ float d_x1[MROWS * 2 * H_];             // [t*B+b][2H]
__device__ float d_pre1[MROWS * 2 * H_];           // [t*B+b][2H]
__device__ float d_out2[MROWS * 2 * H_];           // [b*T+t][2H]
__device__ float d_hh[MROWS * E_];                 // [b*T+t][E]
__device__ float d_bsum0[2 * H_];
__device__ float d_bsum1[2 * H_];

// ---------------------------------------------------------------------------
// Packed fp32x2 helpers (exact fp32 math, 2x FFMA throughput on sm_103a)
// ---------------------------------------------------------------------------
__device__ __forceinline__ ull fma2(ull a, ull b, ull c) {
    ull d;
    asm("fma.rn.f32x2 %0, %1, %2, %3;" : "=l"(d) : "l"(a), "l"(b), "l"(c));
    return d;
}
__device__ __forceinline__ ull dup2(float v) {
    ull r;
    asm("mov.b64 %0, {%1, %1};" : "=l"(r) : "f"(v));
    return r;
}
__device__ __forceinline__ float2 unpack2(ull v) {
    float2 f;
    asm("mov.b64 {%0, %1}, %2;" : "=f"(f.x), "=f"(f.y) : "l"(v));
    return f;
}

// ---------------------------------------------------------------------------
// prep: bsum = bih + bhh for both layers
// ---------------------------------------------------------------------------
__global__ void prep_bias_kernel(const float* __restrict__ bih0, const float* __restrict__ bhh0,
                                 const float* __restrict__ bih1, const float* __restrict__ bhh1) {
    int i = blockIdx.x * 256 + threadIdx.x;   // 0..2047
    if (i < 2 * H_) {
        d_bsum0[i] = bih0[i] + bhh0[i];
        d_bsum1[i] = bih1[i] + bhh1[i];
    }
}

// ---------------------------------------------------------------------------
// expand: d_expanded[b] = relu(LN(x[b] @ Wexp^T + bexp; g1, be1))   [32,1024]
// one block per batch row, 256 threads x 4 outputs
// ---------------------------------------------------------------------------
__global__ __launch_bounds__(256) void expand_kernel(
    const float* __restrict__ x, const float* __restrict__ Wexp,
    const float* __restrict__ bexp, const float* __restrict__ g1,
    const float* __restrict__ be1) {
    __shared__ __align__(16) float xs[512];
    __shared__ float rs[8], rq[8];
    __shared__ float mu_s, rstd_s;
    int b = blockIdx.x, tid = threadIdx.x;
    if (tid < 128) ((float4*)xs)[tid] = ((const float4*)(x + b * 512))[tid];
    __syncthreads();

    float v[4];
#pragma unroll
    for (int i = 0; i < 4; i++) {
        int row = tid + i * 256;
        const float* w = Wexp + (size_t)row * 512;
        float acc = 0.f;
#pragma unroll 8
        for (int k = 0; k < 512; k += 4) {
            float4 wv = *(const float4*)(w + k);
            acc += wv.x * xs[k] + wv.y * xs[k + 1] + wv.z * xs[k + 2] + wv.w * xs[k + 3];
        }
        v[i] = acc + bexp[row];
    }
    float s = v[0] + v[1] + v[2] + v[3];
    float q = v[0] * v[0] + v[1] * v[1] + v[2] * v[2] + v[3] * v[3];
#pragma unroll
    for (int o = 16; o; o >>= 1) {
        s += __shfl_down_sync(0xffffffffu, s, o);
        q += __shfl_down_sync(0xffffffffu, q, o);
    }
    int w = tid >> 5, lane = tid & 31;
    if (!lane) { rs[w] = s; rq[w] = q; }
    __syncthreads();
    if (tid == 0) {
        float S = 0.f, Q = 0.f;
#pragma unroll
        for (int i = 0; i < 8; i++) { S += rs[i]; Q += rq[i]; }
        float mu = S * (1.f / 1024.f);
        float var = Q * (1.f / 1024.f) - mu * mu;
        mu_s = mu;
        rstd_s = rsqrtf(var + 1e-5f);
    }
    __syncthreads();
    float mu = mu_s, rstd = rstd_s;
#pragma unroll
    for (int i = 0; i < 4; i++) {
        int row = tid + i * 256;
        float y = (v[i] - mu) * rstd * g1[row] + be1[row];
        d_expanded[b * H_ + row] = fmaxf(y, 0.f);
    }
}

// ---------------------------------------------------------------------------
// seq[(t*B+b)] = expanded[b] + pos[t]
// ---------------------------------------------------------------------------
__global__ void seq_kernel(const float* __restrict__ pos) {
    int r = blockIdx.x;          // 0..4095
    int t = r >> 5, b = r & 31;
    int tid = threadIdx.x;       // 0..255 (x float4)
    float4 e = ((const float4*)(d_expanded + b * H_))[tid];
    float4 p = ((const float4*)(pos + t * H_))[tid];
    float4 o;
    o.x = e.x + p.x; o.y = e.y + p.y; o.z = e.z + p.z; o.w = e.w + p.w;
    ((float4*)(d_seq + (size_t)r * H_))[tid] = o;
}

// ---------------------------------------------------------------------------
// init hidden state: hbuf[0][0] = hbuf[0][1] = expanded
// ---------------------------------------------------------------------------
__global__ void init_h_kernel() {
    int i = blockIdx.x * 256 + threadIdx.x;  // 8192 float4
    float4 v = ((const float4*)d_expanded)[i];
    ((float4*)d_hbuf[0][0])[i] = v;
    ((float4*)d_hbuf[0][1])[i] = v;
}

// ---------------------------------------------------------------------------
// SGEMM: C[M,N] = A[M,K] @ W[N,K]^T + bias[N]
// 128x128 tile, BK=8, 256 threads, 8x8 per thread, fma.rn.f32x2 accumulation.
// M,N % 128 == 0; K % 8 == 0. A/C selected from device globals by `which`.
// which: 0: seq->pre0  1: x1->pre1  2: out2->hh  3: hh->outp(logits)
// ---------------------------------------------------------------------------
__global__ __launch_bounds__(256, 2) void sgemm_kernel(
    int which, const float* __restrict__ W, const float* __restrict__ bias,
    float* __restrict__ outp, int N, int K) {
    const float* A;
    float* C;
    if (which == 0)      { A = d_seq;  C = d_pre0; }
    else if (which == 1) { A = d_x1;   C = d_pre1; }
    else if (which == 2) { A = d_out2; C = d_hh;   }
    else                 { A = d_hh;   C = outp;   }

    __shared__ __align__(16) float as[2][8][128];
    __shared__ __align__(16) ull  bs[2][8][128];

    const int tid = threadIdx.x;
    const int tx = tid & 15;
    const int ty = tid >> 4;
    const int bm = blockIdx.y * 128;
    const int bn = blockIdx.x * 128;

    const int lrow = tid >> 1;
    const int lk = (tid & 1) * 4;

    const float* Ap = A + (size_t)(bm + lrow) * K + lk;
    const float* Wp = W + (size_t)(bn + lrow) * K + lk;

    ull acc[4][8];
#pragma unroll
    for (int i = 0; i < 4; i++)
#pragma unroll
        for (int j = 0; j < 8; j++) acc[i][j] = 0ull;

    // prologue: tile 0
    float4 ag = *(const float4*)Ap;
    float4 wg = *(const float4*)Wp;
    Ap += 8; Wp += 8;
    as[0][lk + 0][lrow] = ag.x; as[0][lk + 1][lrow] = ag.y;
    as[0][lk + 2][lrow] = ag.z; as[0][lk + 3][lrow] = ag.w;
    bs[0][lk + 0][lrow] = dup2(wg.x); bs[0][lk + 1][lrow] = dup2(wg.y);
    bs[0][lk + 2][lrow] = dup2(wg.z); bs[0][lk + 3][lrow] = dup2(wg.w);
    __syncthreads();

    const int nk = K >> 3;
    for (int kt = 0; kt < nk; kt++) {
        const int buf = kt & 1;
        if (kt + 1 < nk) {
            ag = *(const float4*)Ap;
            wg = *(const float4*)Wp;
            Ap += 8; Wp += 8;
        }
#pragma unroll
        for (int k = 0; k < 8; k++) {
            ulonglong2 a0 = *(const ulonglong2*)&as[buf][k][ty * 4];
            ulonglong2 a1 = *(const ulonglong2*)&as[buf][k][64 + ty * 4];
            ull av0 = a0.x, av1 = a0.y, av2 = a1.x, av3 = a1.y;
            ull bv[8];
#pragma unroll
            for (int j = 0; j < 8; j++) bv[j] = bs[buf][k][tx + 16 * j];
#pragma unroll
            for (int j = 0; j < 8; j++) {
                acc[0][j] = fma2(av0, bv[j], acc[0][j]);
                acc[1][j] = fma2(av1, bv[j], acc[1][j]);
                acc[2][j] = fma2(av2, bv[j], acc[2][j]);
                acc[3][j] = fma2(av3, bv[j], acc[3][j]);
            }
        }
        if (kt + 1 < nk) {
            const int nb = buf ^ 1;
            as[nb][lk + 0][lrow] = ag.x; as[nb][lk + 1][lrow] = ag.y;
            as[nb][lk + 2][lrow] = ag.z; as[nb][lk + 3][lrow] = ag.w;
            bs[nb][lk + 0][lrow] = dup2(wg.x); bs[nb][lk + 1][lrow] = dup2(wg.y);
            bs[nb][lk + 2][lrow] = dup2(wg.z); bs[nb][lk + 3][lrow] = dup2(wg.w);
            __syncthreads();
        }
    }

    // epilogue: bias + store
    float bv[8];
#pragma unroll
    for (int j = 0; j < 8; j++) bv[j] = bias[bn + tx + 16 * j];
#pragma unroll
    for (int i = 0; i < 4; i++) {
        int rb = bm + (i >> 1) * 64 + ty * 4 + (i & 1) * 2;
#pragma unroll
        for (int j = 0; j < 8; j++) {
            float2 v = unpack2(acc[i][j]);
            int c = bn + tx + 16 * j;
            C[(size_t)rb * N + c] = v.x + bv[j];
            C[(size_t)(rb + 1) * N + c] = v.y + bv[j];
        }
    }
}

// ---------------------------------------------------------------------------
// One recurrent step for both directions of one layer.
// grid = 128 blocks (dir = bx>>6, jb = bx&63 -> 16 j columns), 128 threads.
// Thread (j = tid&15, bq = tid>>4): computes h for b = bq + 8*{0..3}.
// h_new = relu(pre[tt-row] + h_prev @ Whh^T); writes hnext + outbuf.
// layer: 0 -> pre0/x1, 1 -> pre1/out2.
// ---------------------------------------------------------------------------
__global__ __launch_bounds__(128) void rnn_step_kernel(
    const float* __restrict__ Whh, int t, int layer,
    int ot_stride, int ob_stride) {
    const int dir = blockIdx.x >> 6;
    const int jb = blockIdx.x & 63;
    const int tid = threadIdx.x;
    const int j = tid & 15;
    const int bq = tid >> 4;

    const float* pre = layer ? d_pre1 : d_pre0;
    float* outbuf = layer ? d_out2 : d_x1;
    const float* hprev = &d_hbuf[t & 1][dir][0];
    float* hnext = &d_hbuf[(t + 1) & 1][dir][0];

    const int tt = dir ? (T_ - 1 - t) : t;
    const float* wbase = Whh + ((size_t)dir * H_ + jb * 16) * H_;

    __shared__ __align__(16) float hs[32][64];
    __shared__ __align__(16) float ws[16][68];

    ull acc[4][2];
#pragma unroll
    for (int o = 0; o < 4; o++) { acc[o][0] = 0ull; acc[o][1] = 0ull; }

    for (int kc = 0; kc < H_; kc += 64) {
        __syncthreads();
        // fill hs: 32x64 floats = 512 float4, 128 threads x 4
#pragma unroll
        for (int i = 0; i < 4; i++) {
            int l = tid + i * 128;
            int r = l >> 4;
            int c = (l & 15) * 4;
            *(float4*)&hs[r][c] = *(const float4*)&hprev[r * H_ + kc + c];
        }
        // fill ws: 16x64 floats = 256 float4, 128 threads x 2 (padded stride 68)
#pragma unroll
        for (int i = 0; i < 2; i++) {
            int l = tid + i * 128;
            int r = l >> 4;
            int c = (l & 15) * 4;
            *(float4*)&ws[r][c] = *(const float4*)&wbase[(size_t)r * H_ + kc + c];
        }
        __syncthreads();
#pragma unroll
        for (int k = 0; k < 64; k += 4) {
            ulonglong2 w2 = *(const ulonglong2*)&ws[j][k];
#pragma unroll
            for (int o = 0; o < 4; o++) {
                ulonglong2 h2 = *(const ulonglong2*)&hs[bq + 8 * o][k];
                acc[o][0] = fma2(h2.x, w2.x, acc[o][0]);
                acc[o][1] = fma2(h2.y, w2.y, acc[o][1]);
            }
        }
    }

    const int col = jb * 16 + j;
#pragma unroll
    for (int o = 0; o < 4; o++) {
        int b = bq + 8 * o;
        float2 p0 = unpack2(acc[o][0]);
        float2 p1 = unpack2(acc[o][1]);
        float v = (p0.x + p0.y) + (p1.x + p1.y);
        float pv = pre[(size_t)(tt * B_ + b) * (2 * H_) + dir * H_ + col];
        float h = fmaxf(v + pv, 0.f);
        hnext[b * H_ + col] = h;
        outbuf[(size_t)tt * ot_stride + (size_t)b * ob_stride + dir * H_ + col] = h;
    }
}

// ---------------------------------------------------------------------------
// LN2 + relu in-place on d_hh rows of 512: relu(LN(v)*g2 + be2)
// ---------------------------------------------------------------------------
__global__ __launch_bounds__(128) void ln2_kernel(const float* __restrict__ g2,
                                                  const float* __restrict__ be2) {
    int r = blockIdx.x, tid = threadIdx.x;
    float* row = d_hh + (size_t)r * E_;
    float4 v = ((float4*)row)[tid];
    float s = v.x + v.y + v.z + v.w;
    float q = v.x * v.x + v.y * v.y + v.z * v.z + v.w * v.w;
#pragma unroll
    for (int o = 16; o; o >>= 1) {
        s += __shfl_down_sync(0xffffffffu, s, o);
        q += __shfl_down_sync(0xffffffffu, q, o);
    }
    __shared__ float rs[4], rq[4];
    __shared__ float mu_s, rstd_s;
    int w = tid >> 5, lane = tid & 31;
    if (!lane) { rs[w] = s; rq[w] = q; }
    __syncthreads();
    if (tid == 0) {
        float S = rs[0] + rs[1] + rs[2] + rs[3];
        float Q = rq[0] + rq[1] + rq[2] + rq[3];
        float mu = S * (1.f / 512.f);
        float var = Q * (1.f / 512.f) - mu * mu;
        mu_s = mu;
        rstd_s = rsqrtf(var + 1e-5f);
    }
    __syncthreads();
    float mu = mu_s, rstd = rstd_s;
    float4 g = ((const float4*)g2)[tid];
    float4 be = ((const float4*)be2)[tid];
    v.x = fmaxf((v.x - mu) * rstd * g.x + be.x, 0.f);
    v.y = fmaxf((v.y - mu) * rstd * g.y + be.y, 0.f);
    v.z = fmaxf((v.z - mu) * rstd * g.z + be.z, 0.f);
    v.w = fmaxf((v.w - mu) * rstd * g.w + be.w, 0.f);
    ((float4*)row)[tid] = v;
}

// ---------------------------------------------------------------------------
// launch
// ---------------------------------------------------------------------------
extern "C" void kernel_launch(void* const* d_in, const int* in_sizes, int n_in,
                              void* d_out, int out_size) {
    const float* x    = (const float*)d_in[0];
    const float* Wexp = (const float*)d_in[1];
    const float* bexp = (const float*)d_in[2];
    const float* g1   = (const float*)d_in[3];
    const float* be1  = (const float*)d_in[4];
    const float* pos  = (const float*)d_in[5];
    const float* Wih0 = (const float*)d_in[6];
    const float* Whh0 = (const float*)d_in[7];
    const float* bih0 = (const float*)d_in[8];
    const float* bhh0 = (const float*)d_in[9];
    const float* Wih1 = (const float*)d_in[10];
    const float* Whh1 = (const float*)d_in[11];
    const float* bih1 = (const float*)d_in[12];
    const float* bhh1 = (const float*)d_in[13];
    const float* Wp1  = (const float*)d_in[14];
    const float* bp1  = (const float*)d_in[15];
    const float* g2   = (const float*)d_in[16];
    const float* be2  = (const float*)d_in[17];
    const float* Wp2  = (const float*)d_in[18];
    const float* bp2  = (const float*)d_in[19];
    float* out = (float*)d_out;

    // bias sums + expand + seq
    prep_bias_kernel<<<8, 256>>>(bih0, bhh0, bih1, bhh1);
    expand_kernel<<<32, 256>>>(x, Wexp, bexp, g1, be1);
    seq_kernel<<<4096, 256>>>(pos);

    // pre0 = seq @ Wih0^T + (bih0+bhh0):  [4096,2048], K=1024
    sgemm_kernel<<<dim3(16, 32), 256>>>(0, Wih0, d_bsum0, nullptr, 2 * H_, H_);

    // layer 0 recurrence -> x1
    init_h_kernel<<<32, 256>>>();
    for (int t = 0; t < T_; t++)
        rnn_step_kernel<<<128, 128>>>(Whh0, t, 0, /*ot*/ B_ * 2 * H_, /*ob*/ 2 * H_);

    // pre1 = x1 @ Wih1^T + (bih1+bhh1):  [4096,2048], K=2048
    sgemm_kernel<<<dim3(16, 32), 256>>>(1, Wih1, d_bsum1, nullptr, 2 * H_, 2 * H_);

    // layer 1 recurrence -> out2 ([b*T+t][2H])
    init_h_kernel<<<32, 256>>>();
    for (int t = 0; t < T_; t++)
        rnn_step_kernel<<<128, 128>>>(Whh1, t, 1, /*ot*/ 2 * H_, /*ob*/ T_ * 2 * H_);

    // projection: hh = out2 @ Wp1^T + bp1  [4096,512], K=2048 ; then LN+relu
    sgemm_kernel<<<dim3(4, 32), 256>>>(2, Wp1, bp1, nullptr, E_, 2 * H_);
    ln2_kernel<<<4096, 128>>>(g2, be2);

    // logits: out = hh @ Wp2^T + bp2  [4096,32000], K=512
    sgemm_kernel<<<dim3(250, 32), 256>>>(3, Wp2, bp2, out, V_, E_);
}